// round 1
// baseline (speedup 1.0000x reference)
#include <cuda_runtime.h>
#include <cuda_bf16.h>
#include <cstdint>

#define N_USERS 50000
#define D 128
#define N_EDGES 800000

// Scratch for weighted = user_emb @ W  (no cudaMalloc allowed)
__device__ float g_weighted[N_USERS * D];

// ---------------------------------------------------------------------------
// Kernel 1: weighted = user_emb @ W   (fp32, register-blocked 4 rows x 4 cols)
// Each warp handles 4 rows; lane covers 4 consecutive cols (float4).
// Block = 256 threads = 8 warps = 32 rows.
// ---------------------------------------------------------------------------
__global__ __launch_bounds__(256) void gemm_kernel(
    const float* __restrict__ emb,   // [N_USERS, D]
    const float* __restrict__ W,     // [D, D]
    float* __restrict__ out)         // [N_USERS, D]
{
    const int warp = threadIdx.x >> 5;
    const int lane = threadIdx.x & 31;
    const int row0 = (blockIdx.x * 8 + warp) * 4;   // 4 rows per warp
    if (row0 >= N_USERS) return;
    const int colbase = lane * 4;

    float4 acc0 = {0.f,0.f,0.f,0.f};
    float4 acc1 = {0.f,0.f,0.f,0.f};
    float4 acc2 = {0.f,0.f,0.f,0.f};
    float4 acc3 = {0.f,0.f,0.f,0.f};

    const float4* e0 = reinterpret_cast<const float4*>(emb + (row0 + 0) * D);
    const float4* e1 = reinterpret_cast<const float4*>(emb + (row0 + 1) * D);
    const float4* e2 = reinterpret_cast<const float4*>(emb + (row0 + 2) * D);
    const float4* e3 = reinterpret_cast<const float4*>(emb + (row0 + 3) * D);

    #pragma unroll 8
    for (int kk = 0; kk < D / 4; kk++) {
        float4 a0 = e0[kk];
        float4 a1 = e1[kk];
        float4 a2 = e2[kk];
        float4 a3 = e3[kk];
        #pragma unroll
        for (int j = 0; j < 4; j++) {
            int k = kk * 4 + j;
            float4 w = *reinterpret_cast<const float4*>(W + k * D + colbase);
            float b0 = (j == 0) ? a0.x : (j == 1) ? a0.y : (j == 2) ? a0.z : a0.w;
            float b1 = (j == 0) ? a1.x : (j == 1) ? a1.y : (j == 2) ? a1.z : a1.w;
            float b2 = (j == 0) ? a2.x : (j == 1) ? a2.y : (j == 2) ? a2.z : a2.w;
            float b3 = (j == 0) ? a3.x : (j == 1) ? a3.y : (j == 2) ? a3.z : a3.w;
            acc0.x += b0 * w.x; acc0.y += b0 * w.y; acc0.z += b0 * w.z; acc0.w += b0 * w.w;
            acc1.x += b1 * w.x; acc1.y += b1 * w.y; acc1.z += b1 * w.z; acc1.w += b1 * w.w;
            acc2.x += b2 * w.x; acc2.y += b2 * w.y; acc2.z += b2 * w.z; acc2.w += b2 * w.w;
            acc3.x += b3 * w.x; acc3.y += b3 * w.y; acc3.z += b3 * w.z; acc3.w += b3 * w.w;
        }
    }

    *reinterpret_cast<float4*>(out + (row0 + 0) * D + colbase) = acc0;
    if (row0 + 1 < N_USERS) *reinterpret_cast<float4*>(out + (row0 + 1) * D + colbase) = acc1;
    if (row0 + 2 < N_USERS) *reinterpret_cast<float4*>(out + (row0 + 2) * D + colbase) = acc2;
    if (row0 + 3 < N_USERS) *reinterpret_cast<float4*>(out + (row0 + 3) * D + colbase) = acc3;
}

// ---------------------------------------------------------------------------
// Kernel 2: out = user_emb   (residual init; out was poisoned)
// ---------------------------------------------------------------------------
__global__ void copy_kernel(const float4* __restrict__ src, float4* __restrict__ dst, int n4)
{
    int i = blockIdx.x * blockDim.x + threadIdx.x;
    if (i < n4) dst[i] = src[i];
}

// ---------------------------------------------------------------------------
// Kernel 3: out[rows[e]] += vals[e] * weighted[cols[e]]
// One warp per edge; lane covers 4 consecutive floats -> red.global.add.v4.f32
// ---------------------------------------------------------------------------
__global__ __launch_bounds__(256) void edge_kernel(
    const int* __restrict__ rows,
    const int* __restrict__ cols,
    const float* __restrict__ vals,
    const float* __restrict__ weighted,
    float* __restrict__ out)
{
    const int warp = (blockIdx.x * blockDim.x + threadIdx.x) >> 5;
    const int lane = threadIdx.x & 31;
    if (warp >= N_EDGES) return;

    const int   r = __ldg(rows + warp);
    const int   c = __ldg(cols + warp);
    const float v = __ldg(vals + warp);

    float4 w = *reinterpret_cast<const float4*>(weighted + (size_t)c * D + lane * 4);
    float px = v * w.x, py = v * w.y, pz = v * w.z, pw = v * w.w;

    float* dst = out + (size_t)r * D + lane * 4;
    asm volatile("red.global.add.v4.f32 [%0], {%1,%2,%3,%4};"
                 :: "l"(dst), "f"(px), "f"(py), "f"(pz), "f"(pw)
                 : "memory");
}

// ---------------------------------------------------------------------------
// Launch
// Inputs (metadata order): user_emb [50000*128] f32, social_weight [128*128] f32,
//                          rows [800000] i32, cols [800000] i32, vals [800000] f32
// Output: [50000*128] f32
// ---------------------------------------------------------------------------
extern "C" void kernel_launch(void* const* d_in, const int* in_sizes, int n_in,
                              void* d_out, int out_size)
{
    const float* user_emb = (const float*)d_in[0];
    const float* social_w = (const float*)d_in[1];
    const int*   rows     = (const int*)d_in[2];
    const int*   cols     = (const int*)d_in[3];
    const float* vals     = (const float*)d_in[4];
    float*       out      = (float*)d_out;

    float* weighted = nullptr;
    cudaGetSymbolAddress((void**)&weighted, g_weighted);

    // 1. weighted = user_emb @ W
    {
        int rows_per_block = 32;
        int nblk = (N_USERS + rows_per_block - 1) / rows_per_block;
        gemm_kernel<<<nblk, 256>>>(user_emb, social_w, weighted);
    }

    // 2. out = user_emb
    {
        int n4 = N_USERS * D / 4;
        copy_kernel<<<(n4 + 255) / 256, 256>>>(
            (const float4*)user_emb, (float4*)out, n4);
    }

    // 3. scatter-add edges
    {
        long long total_threads = (long long)N_EDGES * 32;
        int nblk = (int)((total_threads + 255) / 256);
        edge_kernel<<<nblk, 256>>>(rows, cols, vals, weighted, out);
    }
}

// round 2
// speedup vs baseline: 1.5317x; 1.5317x over previous
#include <cuda_runtime.h>
#include <cuda_bf16.h>
#include <cstdint>

#define N_USERS 50000
#define D 128
#define N_EDGES 800000

// Scratch for weighted = user_emb @ W  (no cudaMalloc allowed)
__device__ float g_weighted[N_USERS * D];

// ---------------------------------------------------------------------------
// Kernel 1: weighted = user_emb @ W
// W staged fully in shared memory (64 KB dynamic smem).
// Block = 256 threads = 8 warps; each warp computes 8 rows x (lane: 4 cols).
// Block covers 64 rows. FMA-pipe bound by design.
// ---------------------------------------------------------------------------
__global__ __launch_bounds__(256) void gemm_kernel(
    const float* __restrict__ emb,   // [N_USERS, D]
    const float* __restrict__ W,     // [D, D]
    float* __restrict__ out)         // [N_USERS, D]
{
    extern __shared__ float Ws[];    // [D * D] = 64 KB

    // Cooperative load of W into smem: 256 threads x float4 = 4 KB/iter, 16 iters
    {
        const float4* Wg4 = reinterpret_cast<const float4*>(W);
        float4* Ws4 = reinterpret_cast<float4*>(Ws);
        #pragma unroll
        for (int i = 0; i < (D * D / 4) / 256; i++) {
            Ws4[i * 256 + threadIdx.x] = Wg4[i * 256 + threadIdx.x];
        }
    }
    __syncthreads();

    const int warp = threadIdx.x >> 5;
    const int lane = threadIdx.x & 31;
    const int row0 = (blockIdx.x * 8 + warp) * 8;   // 8 rows per warp
    if (row0 >= N_USERS) return;
    const int colbase = lane * 4;
    const bool full = (row0 + 8 <= N_USERS);

    float4 acc[8];
    #pragma unroll
    for (int r = 0; r < 8; r++) acc[r] = make_float4(0.f, 0.f, 0.f, 0.f);

    const float4* erow[8];
    #pragma unroll
    for (int r = 0; r < 8; r++) {
        int rr = full ? (row0 + r) : min(row0 + r, N_USERS - 1);
        erow[r] = reinterpret_cast<const float4*>(emb + (size_t)rr * D);
    }

    #pragma unroll 4
    for (int kk = 0; kk < D / 4; kk++) {
        float4 a[8];
        #pragma unroll
        for (int r = 0; r < 8; r++) a[r] = erow[r][kk];

        #pragma unroll
        for (int j = 0; j < 4; j++) {
            const int k = kk * 4 + j;
            float4 w = *reinterpret_cast<const float4*>(Ws + k * D + colbase);
            #pragma unroll
            for (int r = 0; r < 8; r++) {
                float b = (j == 0) ? a[r].x : (j == 1) ? a[r].y
                        : (j == 2) ? a[r].z : a[r].w;
                acc[r].x += b * w.x;
                acc[r].y += b * w.y;
                acc[r].z += b * w.z;
                acc[r].w += b * w.w;
            }
        }
    }

    #pragma unroll
    for (int r = 0; r < 8; r++) {
        if (full || (row0 + r) < N_USERS)
            *reinterpret_cast<float4*>(out + (size_t)(row0 + r) * D + colbase) = acc[r];
    }
}

// ---------------------------------------------------------------------------
// Kernel 2: out = user_emb   (residual init; out was poisoned)
// ---------------------------------------------------------------------------
__global__ void copy_kernel(const float4* __restrict__ src, float4* __restrict__ dst, int n4)
{
    int i = blockIdx.x * blockDim.x + threadIdx.x;
    if (i < n4) dst[i] = src[i];
}

// ---------------------------------------------------------------------------
// Kernel 3: out[rows[e]] += vals[e] * weighted[cols[e]]
// One warp per edge; lane covers 4 consecutive floats -> red.global.add.v4.f32
// ---------------------------------------------------------------------------
__global__ __launch_bounds__(256) void edge_kernel(
    const int* __restrict__ rows,
    const int* __restrict__ cols,
    const float* __restrict__ vals,
    const float* __restrict__ weighted,
    float* __restrict__ out)
{
    const int warp = (blockIdx.x * blockDim.x + threadIdx.x) >> 5;
    const int lane = threadIdx.x & 31;
    if (warp >= N_EDGES) return;

    const int   r = __ldg(rows + warp);
    const int   c = __ldg(cols + warp);
    const float v = __ldg(vals + warp);

    float4 w = *reinterpret_cast<const float4*>(weighted + (size_t)c * D + lane * 4);
    float px = v * w.x, py = v * w.y, pz = v * w.z, pw = v * w.w;

    float* dst = out + (size_t)r * D + lane * 4;
    asm volatile("red.global.add.v4.f32 [%0], {%1,%2,%3,%4};"
                 :: "l"(dst), "f"(px), "f"(py), "f"(pz), "f"(pw)
                 : "memory");
}

// ---------------------------------------------------------------------------
// Launch
// Inputs (metadata order): user_emb [50000*128] f32, social_weight [128*128] f32,
//                          rows [800000] i32, cols [800000] i32, vals [800000] f32
// Output: [50000*128] f32
// ---------------------------------------------------------------------------
extern "C" void kernel_launch(void* const* d_in, const int* in_sizes, int n_in,
                              void* d_out, int out_size)
{
    const float* user_emb = (const float*)d_in[0];
    const float* social_w = (const float*)d_in[1];
    const int*   rows     = (const int*)d_in[2];
    const int*   cols     = (const int*)d_in[3];
    const float* vals     = (const float*)d_in[4];
    float*       out      = (float*)d_out;

    float* weighted = nullptr;
    cudaGetSymbolAddress((void**)&weighted, g_weighted);

    // 1. weighted = user_emb @ W  (64 KB dynamic smem for W)
    {
        const int smem_bytes = D * D * sizeof(float);  // 65536
        cudaFuncSetAttribute(gemm_kernel,
                             cudaFuncAttributeMaxDynamicSharedMemorySize, smem_bytes);
        int rows_per_block = 64;                        // 8 warps x 8 rows
        int nblk = (N_USERS + rows_per_block - 1) / rows_per_block;
        gemm_kernel<<<nblk, 256, smem_bytes>>>(user_emb, social_w, weighted);
    }

    // 2. out = user_emb
    {
        int n4 = N_USERS * D / 4;
        copy_kernel<<<(n4 + 255) / 256, 256>>>(
            (const float4*)user_emb, (float4*)out, n4);
    }

    // 3. scatter-add edges
    {
        long long total_threads = (long long)N_EDGES * 32;
        int nblk = (int)((total_threads + 255) / 256);
        edge_kernel<<<nblk, 256>>>(rows, cols, vals, weighted, out);
    }
}